// round 8
// baseline (speedup 1.0000x reference)
#include <cuda_runtime.h>

#define NS       8192
#define NC       1024
#define NK       4
#define TILE     32            // channels per block tile
#define THREADS  128
#define SPT      2             // samples per thread (sequential rounds)
#define PAD      4
#define WROW     40            // words per comp row (160B, 16B multiple)
#define OFF2     (NK * WROW)   // start of the +2-shifted copy
#define SROW     36            // staging row stride in words (conflict-free)

__global__ void __launch_bounds__(THREADS)
smf_kernel(const float* __restrict__ comp,      // [4, 1024]
           const float* __restrict__ contrib,   // [8192, 4]
           const float* __restrict__ shift,     // [8192, 4]
           float* __restrict__ out)             // [8192, 1024]
{
    __shared__ __align__(16) float sc[2 * NK * WROW];    // window + (+2)-shifted copy
    __shared__ __align__(16) float st[THREADS * SROW];   // staging (reused per round)

    const int tid  = threadIdx.x;
    const int tile = blockIdx.x & 31;
    const int grp  = blockIdx.x >> 5;
    const int c0   = tile * TILE;

    // ---- fill both window copies: sc[k][w]=comp[c0-4+w], sc2[k][w]=comp[c0-2+w] ----
    for (int idx = tid; idx < 2 * NK * WROW; idx += THREADS) {
        const int copy = idx / (NK * WROW);
        const int rem  = idx - copy * (NK * WROW);
        const int k = rem / WROW, w = rem - k * WROW;
        const int j = c0 - PAD + w + 2 * copy;
        sc[idx] = (j >= 0 && j < NC) ? comp[k * NC + j] : 0.0f;
    }

    // prefetch params for both rounds (hide gmem latency under round-0 compute)
    const int sA = grp * (THREADS * SPT) + tid;
    float4 shp[SPT], cnp[SPT];
    #pragma unroll
    for (int r = 0; r < SPT; r++) {
        shp[r] = __ldg((const float4*)(shift   + (sA + r * THREADS) * NK));
        cnp[r] = __ldg((const float4*)(contrib + (sA + r * THREADS) * NK));
    }
    __syncthreads();

    #pragma unroll
    for (int r = 0; r < SPT; r++) {
        const float shv[NK] = { shp[r].x, shp[r].y, shp[r].z, shp[r].w };
        const float cnv[NK] = { cnp[r].x, cnp[r].y, cnp[r].z, cnp[r].w };

        float w0[NK], w1[NK], w2[NK];
        int   base[NK];
        #pragma unroll
        for (int k = 0; k < NK; k++) {
            const float sh = shv[k];
            const float cn = cnv[k];
            int fi = (int)floorf(sh);
            fi = max(-4, min(3, fi));            // shift == 4.0 edge folds into w2
            const int   g = fi & ~1;             // even base in {-4,-2,0,2}
            const float x = sh - (float)g;       // in [0, 2]
            w0[k] = cn * fmaxf(0.0f, 1.0f - fabsf(x));
            w1[k] = cn * fmaxf(0.0f, 1.0f - fabsf(1.0f - x));
            w2[k] = cn * fmaxf(0.0f, 1.0f - fabsf(2.0f - x));
            // 4-aligned base: g in {-4,0} -> sc at g+4; g in {-2,2} -> sc2 at g+2
            const bool odd2 = (g & 2) != 0;
            base[k] = (odd2 ? OFF2 : 0) + k * WROW + (odd2 ? (g + 2) : (g + 4));
        }

        // rolling float4 per k
        float4 u[NK];
        #pragma unroll
        for (int k = 0; k < NK; k++) u[k] = *(const float4*)&sc[base[k]];

        float4* myst = (float4*)(st + tid * SROW);
        #pragma unroll
        for (int q = 0; q < TILE / 4; q++) {     // channels 4q .. 4q+3
            float a0 = 0.f, a1 = 0.f, a2 = 0.f, a3 = 0.f;
            #pragma unroll
            for (int k = 0; k < NK; k++) {
                const float4 v = *(const float4*)&sc[base[k] + 4 * q + 4];
                a0 += w0[k] * u[k].x + w1[k] * u[k].y + w2[k] * u[k].z;
                a1 += w0[k] * u[k].y + w1[k] * u[k].z + w2[k] * u[k].w;
                a2 += w0[k] * u[k].z + w1[k] * u[k].w + w2[k] * v.x;
                a3 += w0[k] * u[k].w + w1[k] * v.x   + w2[k] * v.y;
                u[k] = v;
            }
            myst[q] = make_float4(a0, a1, a2, a3);   // STS.128, conflict-free
        }
        __syncthreads();

        // ---- coalesced tile store: 128 samples x 8 float4 each ----
        #pragma unroll
        for (int j2 = 0; j2 < 8; j2++) {
            const int flat = j2 * THREADS + tid;  // 0..1023
            const int sl   = flat >> 3;           // local sample 0..127
            const int q    = flat & 7;
            const float4 v = ((const float4*)st)[sl * (SROW / 4) + q];
            ((float4*)out)[(size_t)(grp * (THREADS * SPT) + r * THREADS + sl) * (NC / 4)
                           + (c0 >> 2) + q] = v;
        }
        if (r + 1 < SPT) __syncthreads();
    }
}

extern "C" void kernel_launch(void* const* d_in, const int* in_sizes, int n_in,
                              void* d_out, int out_size)
{
    // inputs [8192,1024] (ignored), components [4,1024],
    // contributions [8192,4], shift [8192,4]
    const float* comp    = (const float*)d_in[1];
    const float* contrib = (const float*)d_in[2];
    const float* shift   = (const float*)d_in[3];
    float* out           = (float*)d_out;

    smf_kernel<<<32 * 32, THREADS>>>(comp, contrib, shift, out);   // 1024 blocks
}

// round 9
// speedup vs baseline: 1.0070x; 1.0070x over previous
#include <cuda_runtime.h>

#define NS       8192
#define NC       1024
#define NK       4
#define TILE     32            // channels per block tile
#define THREADS  128           // samples per block (1 per thread)
#define PAD      4
#define WROW     40            // words per comp window row
#define OFF1     164           // start of the +1-shifted copy (4 mod 32 banks)
#define SROW     36            // staging row stride (16B-aligned, conflict-free)

__global__ void __launch_bounds__(THREADS)
smf_kernel(const float* __restrict__ comp,      // [4, 1024]
           const float* __restrict__ contrib,   // [8192, 4]
           const float* __restrict__ shift,     // [8192, 4]
           float* __restrict__ out)             // [8192, 1024]
{
    __shared__ __align__(16) float sc[OFF1 + NK * WROW]; // copy0 + copy1(+1 word)
    __shared__ __align__(16) float st[THREADS * SROW];   // staging tile

    const int tid  = threadIdx.x;
    const int tile = blockIdx.x & 31;           // 32 channel tiles
    const int grp  = blockIdx.x >> 5;           // 64 sample groups
    const int c0   = tile * TILE;
    const int s    = grp * THREADS + tid;

    // prefetch per-sample params first (hide LDG latency under window fill)
    const float4 sh4 = __ldg((const float4*)(shift   + s * NK));
    const float4 cn4 = __ldg((const float4*)(contrib + s * NK));

    // ---- fill windows: copy0[k][w]=comp[k,c0-4+w], copy1[k][w]=comp[k,c0-3+w] ----
    for (int idx = tid; idx < 2 * NK * WROW; idx += THREADS) {
        const int cpy = idx >= NK * WROW;
        const int rem = idx - cpy * (NK * WROW);
        const int k = rem / WROW, w = rem - k * WROW;
        const int j = c0 - PAD + w + cpy;
        sc[cpy * OFF1 + k * WROW + w] = (j >= 0 && j < NC) ? comp[k * NC + j] : 0.0f;
    }

    const float shv[NK] = { sh4.x, sh4.y, sh4.z, sh4.w };
    const float cnv[NK] = { cn4.x, cn4.y, cn4.z, cn4.w };

    float a[NK], b[NK];
    int   base[NK];
    #pragma unroll
    for (int k = 0; k < NK; k++) {
        const float sh = shv[k];
        const float cn = cnv[k];
        int   fi = (int)floorf(sh);             // in [-4, 4]
        float fr = sh - (float)fi;
        if (fi > 3)  { fr += (float)(fi - 3); fi = 3; }   // shift==4.0 edge
        if (fi < -4) { fi = -4; }
        b[k] = cn * fr;                         // weight of tap fi+1
        a[k] = cn - b[k];                       // cn*(1-fr)
        // parity-matched, 2-aligned base: even fi -> copy0 @ fi+4, odd -> copy1 @ fi+3
        const bool odd = (fi & 1) != 0;
        base[k] = (odd ? OFF1 : 0) + k * WROW + (odd ? (fi + 3) : (fi + 4));
    }
    __syncthreads();

    // ---- main: per 2 channels per k: 1 LDS.64 + 4 FFMA (rolling) ----
    float2 u[NK];
    #pragma unroll
    for (int k = 0; k < NK; k++) u[k] = *(const float2*)&sc[base[k]];

    float4* myst = (float4*)(st + tid * SROW);
    float4 buf;
    #pragma unroll
    for (int ip = 0; ip < TILE / 2; ip++) {     // channels 2ip, 2ip+1
        float a0 = 0.f, a1 = 0.f;
        #pragma unroll
        for (int k = 0; k < NK; k++) {
            const float2 v = *(const float2*)&sc[base[k] + 2 * ip + 2];
            a0 += a[k] * u[k].x + b[k] * u[k].y;
            a1 += a[k] * u[k].y + b[k] * v.x;
            u[k] = v;
        }
        if (ip & 1) { buf.z = a0; buf.w = a1; myst[ip >> 1] = buf; }
        else        { buf.x = a0; buf.y = a1; }
    }
    __syncthreads();

    // ---- coalesced tile store: 128 samples x 8 float4 each ----
    #pragma unroll
    for (int j2 = 0; j2 < 8; j2++) {
        const int flat = j2 * THREADS + tid;    // 0..1023
        const int sl   = flat >> 3;             // local sample 0..127
        const int q    = flat & 7;
        const float4 v = ((const float4*)st)[sl * (SROW / 4) + q];
        ((float4*)out)[(size_t)(grp * THREADS + sl) * (NC / 4) + (c0 >> 2) + q] = v;
    }
}

extern "C" void kernel_launch(void* const* d_in, const int* in_sizes, int n_in,
                              void* d_out, int out_size)
{
    // inputs [8192,1024] (ignored), components [4,1024],
    // contributions [8192,4], shift [8192,4]
    const float* comp    = (const float*)d_in[1];
    const float* contrib = (const float*)d_in[2];
    const float* shift   = (const float*)d_in[3];
    float* out           = (float*)d_out;

    smf_kernel<<<32 * 64, THREADS>>>(comp, contrib, shift, out);   // 2048 blocks
}

// round 10
// speedup vs baseline: 1.2806x; 1.2717x over previous
#include <cuda_runtime.h>

#define NS       8192
#define NC       1024
#define NK       4
#define TILE     32            // channels per block tile
#define THREADS  128           // samples per block (1 per thread)
#define PAD      4
#define WROW     40            // words per comp window row
#define OFF1     172           // +1-shifted copy offset; 171+/-7 avoids 0 mod 32 -> no bank aliasing
#define SROW     36            // staging row stride (16B-aligned, conflict-free)

__global__ void __launch_bounds__(THREADS)
smf_kernel(const float* __restrict__ comp,      // [4, 1024]
           const float* __restrict__ contrib,   // [8192, 4]
           const float* __restrict__ shift,     // [8192, 4]
           float* __restrict__ out)             // [8192, 1024]
{
    __shared__ __align__(16) float sc[OFF1 + NK * WROW]; // copy0 + copy1(+1 word)
    __shared__ __align__(16) float st[THREADS * SROW];   // staging tile

    const int tid  = threadIdx.x;
    const int tile = blockIdx.x & 31;           // 32 channel tiles
    const int grp  = blockIdx.x >> 5;           // 64 sample groups
    const int c0   = tile * TILE;
    const int s    = grp * THREADS + tid;

    // prefetch per-sample params first (hide LDG latency under window fill)
    const float4 sh4 = __ldg((const float4*)(shift   + s * NK));
    const float4 cn4 = __ldg((const float4*)(contrib + s * NK));

    // ---- fill windows: copy0[k][w]=comp[k,c0-4+w], copy1[k][w]=comp[k,c0-3+w] ----
    for (int idx = tid; idx < 2 * NK * WROW; idx += THREADS) {
        const int cpy = idx >= NK * WROW;
        const int rem = idx - cpy * (NK * WROW);
        const int k = rem / WROW, w = rem - k * WROW;
        const int j = c0 - PAD + w + cpy;
        sc[cpy * OFF1 + k * WROW + w] = (j >= 0 && j < NC) ? comp[k * NC + j] : 0.0f;
    }

    const float shv[NK] = { sh4.x, sh4.y, sh4.z, sh4.w };
    const float cnv[NK] = { cn4.x, cn4.y, cn4.z, cn4.w };

    float a[NK], b[NK];
    int   base[NK];
    #pragma unroll
    for (int k = 0; k < NK; k++) {
        const float sh = shv[k];
        const float cn = cnv[k];
        int   fi = (int)floorf(sh);             // in [-4, 4]
        float fr = sh - (float)fi;
        if (fi > 3)  { fr += (float)(fi - 3); fi = 3; }   // shift==4.0 edge
        if (fi < -4) { fi = -4; }
        b[k] = cn * fr;                         // weight of tap fi+1
        a[k] = cn - b[k];                       // cn*(1-fr)
        // parity-matched, 2-aligned base: even fi -> copy0 @ fi+4, odd -> copy1 @ fi+3
        const bool odd = (fi & 1) != 0;
        base[k] = (odd ? OFF1 : 0) + k * WROW + (odd ? (fi + 3) : (fi + 4));
    }
    __syncthreads();

    // ---- main: per 2 channels per k: 1 LDS.64 + 4 FFMA (rolling) ----
    float2 u[NK];
    #pragma unroll
    for (int k = 0; k < NK; k++) u[k] = *(const float2*)&sc[base[k]];

    float4* myst = (float4*)(st + tid * SROW);
    float4 buf;
    #pragma unroll
    for (int ip = 0; ip < TILE / 2; ip++) {     // channels 2ip, 2ip+1
        float a0 = 0.f, a1 = 0.f;
        #pragma unroll
        for (int k = 0; k < NK; k++) {
            const float2 v = *(const float2*)&sc[base[k] + 2 * ip + 2];
            a0 += a[k] * u[k].x + b[k] * u[k].y;
            a1 += a[k] * u[k].y + b[k] * v.x;
            u[k] = v;
        }
        if (ip & 1) { buf.z = a0; buf.w = a1; myst[ip >> 1] = buf; }
        else        { buf.x = a0; buf.y = a1; }
    }
    __syncthreads();

    // ---- coalesced tile store: 128 samples x 8 float4 each ----
    #pragma unroll
    for (int j2 = 0; j2 < 8; j2++) {
        const int flat = j2 * THREADS + tid;    // 0..1023
        const int sl   = flat >> 3;             // local sample 0..127
        const int q    = flat & 7;
        const float4 v = ((const float4*)st)[sl * (SROW / 4) + q];
        ((float4*)out)[(size_t)(grp * THREADS + sl) * (NC / 4) + (c0 >> 2) + q] = v;
    }
}

extern "C" void kernel_launch(void* const* d_in, const int* in_sizes, int n_in,
                              void* d_out, int out_size)
{
    // inputs [8192,1024] (ignored), components [4,1024],
    // contributions [8192,4], shift [8192,4]
    const float* comp    = (const float*)d_in[1];
    const float* contrib = (const float*)d_in[2];
    const float* shift   = (const float*)d_in[3];
    float* out           = (float*)d_out;

    smf_kernel<<<32 * 64, THREADS>>>(comp, contrib, shift, out);   // 2048 blocks
}